// round 5
// baseline (speedup 1.0000x reference)
#include <cuda_runtime.h>

#define BB   64
#define HH   384
#define NPLT 16
#define NG   25
#define CAND 625   // NG*NG
#define LF   400   // HH + NPLT

#define LOG2E_F  1.4426950408889634f
#define LOG2PI_F 1.8378770664093453f

// persistent scratch (allocation-free rule: __device__ globals)
__device__ float g_xlim[NG];
__device__ float g_ylim[NG];
__device__ float g_S[BB * CAND];
__device__ float g_pred[BB * NPLT * 2];
__device__ float g_c2;    // (0.5/sigma^2) * LOG2E
__device__ float g_beta;

__device__ __forceinline__ float ex2f(float x) {
    float r;
    asm("ex2.approx.ftz.f32 %0, %1;" : "=f"(r) : "f"(x));
    return r;
}

// ---------------------------------------------------------------------------
// Kernel 1: direct base S (MUFU-streaming, at the MUFU throughput floor).
//   S[b][k] = sum_{j<384} exp(beta*t_j - c*||p_k - h_j||^2)
// grid (5 chunks, 64 batches), 128 threads; 125 candidates per chunk.
// Bounds/grid/constants folded in via warp-level shfl reductions.
//
// Reference semantics for the grid bounds (nd[:, 0] / nd[:, 1]):
//   minx/maxx = min/max over BOTH coordinates of history POINT 0 (all batches)
//   miny/maxy = min/max over BOTH coordinates of history POINT 1 (all batches)
// Warp w (w in {0,1}) reduces over point index w, both dims, 64 batches.
// ---------------------------------------------------------------------------
__global__ void k_base(const float* __restrict__ itime,
                       const float* __restrict__ hist,
                       const float* __restrict__ beta_p,
                       const float* __restrict__ logsig_p) {
    __shared__ float sx[HH], sy[HH], sbt[HH];
    __shared__ float xl[NG], yl[NG];
    __shared__ float bounds[4];  // minx, maxx, miny, maxy

    const int b = blockIdx.y;
    const int t = threadIdx.x;
    const int w = t >> 5, lane = t & 31;

    // ---- bounds: warp w handles history point index w (both dims) ----
    if (w < 2) {
        float a0 = hist[lane * (HH * 2) + 2 * w + 0];         // batch lane, dim 0
        float a1 = hist[lane * (HH * 2) + 2 * w + 1];         // batch lane, dim 1
        float b0 = hist[(lane + 32) * (HH * 2) + 2 * w + 0];  // batch lane+32
        float b1 = hist[(lane + 32) * (HH * 2) + 2 * w + 1];
        float mn = fminf(fminf(a0, a1), fminf(b0, b1));
        float mx = fmaxf(fmaxf(a0, a1), fmaxf(b0, b1));
#pragma unroll
        for (int o = 16; o; o >>= 1) {
            mn = fminf(mn, __shfl_xor_sync(0xffffffffu, mn, o));
            mx = fmaxf(mx, __shfl_xor_sync(0xffffffffu, mx, o));
        }
        if (lane == 0) { bounds[2 * w] = mn; bounds[2 * w + 1] = mx; }
    }

    const float beta = beta_p[0];
    const float sig  = __expf(logsig_p[0]);
    const float c2   = (0.5f / (sig * sig)) * LOG2E_F;

    // ---- history tiles into smem ----
    for (int j = t; j < HH; j += 128) {
        sx[j]  = hist[b * (HH * 2) + 2 * j];
        sy[j]  = hist[b * (HH * 2) + 2 * j + 1];
        sbt[j] = beta * itime[b * HH + j] * LOG2E_F;
    }
    __syncthreads();

    if (t < NG) {
        float minx = bounds[0], maxx = bounds[1];
        float miny = bounds[2], maxy = bounds[3];
        float fx = (t == NG - 1) ? maxx : minx + (maxx - minx) * ((float)t / (float)(NG - 1));
        float fy = (t == NG - 1) ? maxy : miny + (maxy - miny) * ((float)t / (float)(NG - 1));
        xl[t] = fx; yl[t] = fy;
        if (blockIdx.x == 0 && blockIdx.y == 0) { g_xlim[t] = fx; g_ylim[t] = fy; }
    }
    if (t == 0 && blockIdx.x == 0 && blockIdx.y == 0) { g_c2 = c2; g_beta = beta; }
    __syncthreads();

    if (t < 125) {
        int k = blockIdx.x * 125 + t;
        float cx = xl[k % NG];
        float cy = yl[k / NG];
        float s = 0.f;
#pragma unroll 4
        for (int j = 0; j < HH; j++) {
            float dx = cx - sx[j];
            float dy = cy - sy[j];
            float sq = fmaf(dx, dx, dy * dy);
            s += ex2f(fmaf(-c2, sq, sbt[j]));
        }
        g_S[b * CAND + k] = s;
    }
}

// ---------------------------------------------------------------------------
// Kernel 2: 16-step sequential argmin loop. ONE WARP per batch, zero barriers.
// Each lane owns 20 candidates in registers. argmin(ll) == argmin(S);
// first-index tie-break via packed (float_bits(S)<<32 | idx) min (S >= 0).
// Also initializes out[b] with logp0 + constant terms for k_gmm's atomics.
// ---------------------------------------------------------------------------
__global__ void k_iter(const float* __restrict__ curr,
                       const float* __restrict__ hist,
                       const float* __restrict__ logsig_p,
                       float* __restrict__ out) {
    const int b = blockIdx.x;
    const int lane = threadIdx.x;  // 32
    const float c2 = g_c2, beta = g_beta;

    if (lane == 0) {
        float x0 = hist[b * (HH * 2)];
        float y0 = hist[b * (HH * 2) + 1];
        float ls = logsig_p[0];
        float C = 2.f * ls + LOG2PI_F;
        out[b] = -0.5f * (x0 * x0 + y0 * y0) - LOG2PI_F - (float)(LF - 1) * C;
    }

    const int NR = 20;  // ceil(625/32)
    float s[NR], cx[NR], cy[NR];
#pragma unroll
    for (int r = 0; r < NR; r++) {
        int k = lane + 32 * r;
        if (k < CAND) {
            cx[r] = g_xlim[k % NG];
            cy[r] = g_ylim[k / NG];
            s[r]  = g_S[b * CAND + k];
        } else {
            s[r] = 0.f; cx[r] = 0.f; cy[r] = 0.f;
        }
    }

    for (int i = 0; i < NPLT; i++) {
        unsigned long long best = 0xFFFFFFFFFFFFFFFFULL;
#pragma unroll
        for (int r = 0; r < NR; r++) {
            int k = lane + 32 * r;
            if (k < CAND) {
                unsigned long long key =
                    (((unsigned long long)__float_as_uint(s[r])) << 32) | (unsigned)k;
                best = (key < best) ? key : best;
            }
        }
#pragma unroll
        for (int o = 16; o; o >>= 1) {
            unsigned long long other = __shfl_xor_sync(0xffffffffu, best, o);
            best = (other < best) ? other : best;
        }
        unsigned idx = (unsigned)(best & 0xffffffffu);
        float px = g_xlim[idx % NG];
        float py = g_ylim[idx / NG];

        if (lane == 0) {
            out[BB + (i * BB + b) * 2 + 0] = px;
            out[BB + (i * BB + b) * 2 + 1] = py;
            g_pred[(b * NPLT + i) * 2 + 0] = px;
            g_pred[(b * NPLT + i) * 2 + 1] = py;
        }
        if (i < NPLT - 1) {
            float bt = beta * __ldg(&curr[b * NPLT + i]) * LOG2E_F;
#pragma unroll
            for (int r = 0; r < NR; r++) {
                float dx = cx[r] - px;
                float dy = cy[r] - py;
                float sq = fmaf(dx, dx, dy * dy);
                s[r] += ex2f(fmaf(-c2, sq, bt));
            }
        }
    }
}

// ---------------------------------------------------------------------------
// Kernel 3: final GMM log-likelihood.
//   logp_i = log(sum_{j<i} e_j * g_ij) - log(sum_{j<i} e_j) - C
// with e_j = exp(beta*t_j) precomputed (the exp(-beta*t_i) factor cancels),
// g_ij = exp(-c*sq). Grid (8 chunks, 64 batches), 128 thr, warp-per-row,
// atomicAdd partial sums into out[b] (pre-initialized by k_iter).
// ---------------------------------------------------------------------------
__global__ void k_gmm(const float* __restrict__ itime,
                      const float* __restrict__ hist,
                      const float* __restrict__ curr,
                      float* __restrict__ out) {
    __shared__ float exj[LF], px[LF], py[LF];
    const int b = blockIdx.y;
    const int c = blockIdx.x;   // 8 chunks
    const int t = threadIdx.x;  // 128
    const float beta = g_beta, c2 = g_c2;

    for (int j = t; j < HH; j += 128) {
        px[j]  = hist[b * (HH * 2) + 2 * j];
        py[j]  = hist[b * (HH * 2) + 2 * j + 1];
        exj[j] = ex2f(beta * itime[b * HH + j] * LOG2E_F);
    }
    if (t < NPLT) {
        px[HH + t]  = g_pred[(b * NPLT + t) * 2 + 0];
        py[HH + t]  = g_pred[(b * NPLT + t) * 2 + 1];
        exj[HH + t] = ex2f(beta * curr[b * NPLT + t] * LOG2E_F);
    }
    __syncthreads();

    const int w = t >> 5, lane = t & 31;
    float acc = 0.f;

    for (int i = 1 + c * 4 + w; i < LF; i += 32) {
        float xi = px[i], yi = py[i];
        float s1 = 0.f, s2 = 0.f;
        for (int j = lane; j < i; j += 32) {
            float e = exj[j];
            float dx = xi - px[j];
            float dy = yi - py[j];
            float sq = fmaf(dx, dx, dy * dy);
            s1 += e;
            s2 = fmaf(e, ex2f(-c2 * sq), s2);
        }
#pragma unroll
        for (int o = 16; o; o >>= 1) {
            s1 += __shfl_down_sync(0xffffffffu, s1, o);
            s2 += __shfl_down_sync(0xffffffffu, s2, o);
        }
        if (lane == 0) acc += logf(s2) - logf(s1);
    }
    if (lane == 0) atomicAdd(&out[b], acc);
}

// ---------------------------------------------------------------------------
extern "C" void kernel_launch(void* const* d_in, const int* in_sizes, int n_in,
                              void* d_out, int out_size) {
    const float* curr   = (const float*)d_in[0];  // (64,16)
    const float* itime  = (const float*)d_in[1];  // (64,384)
    const float* hist   = (const float*)d_in[2];  // (64,384,2)
    // d_in[3..5] (expected_data, aux_*) are dead inputs
    const float* beta   = (const float*)d_in[6];
    const float* logsig = (const float*)d_in[7];
    float* out = (float*)d_out;  // [64 loglik][16*64*2 predicted]

    k_base<<<dim3(5, BB), 128>>>(itime, hist, beta, logsig);
    k_iter<<<BB, 32>>>(curr, hist, logsig, out);
    k_gmm<<<dim3(8, BB), 128>>>(itime, hist, curr, out);
}

// round 6
// speedup vs baseline: 1.9895x; 1.9895x over previous
#include <cuda_runtime.h>

#define BB   64
#define HH   384
#define NPLT 16
#define NG   25
#define CAND 625   // NG*NG
#define LF   400   // HH + NPLT
#define JS   3     // j-splits in k_base (3 * 128 = 384)

#define LOG2E_F  1.4426950408889634f
#define LOG2PI_F 1.8378770664093453f

// persistent scratch (allocation-free rule: __device__ globals)
__device__ float g_xlim[NG];
__device__ float g_ylim[NG];
__device__ float g_Spart[JS][BB * CAND];
__device__ float g_pred[BB * NPLT * 2];
__device__ float g_c2;    // (0.5/sigma^2) * LOG2E
__device__ float g_beta;

__device__ __forceinline__ float ex2f(float x) {
    float r;
    asm("ex2.approx.ftz.f32 %0, %1;" : "=f"(r) : "f"(x));
    return r;
}

// ---------------------------------------------------------------------------
// Kernel 1: base S partials.
//   S[b][k] = sum_j exp(beta*t_j - c*||p_k - h_j||^2), j split 3 ways.
// grid (5 cand-chunks, 64 batches, 3 j-splits), 128 threads.
// Each block handles 125 candidates x 128 history entries -> g_Spart[js].
// float4-packed smem tile (1 LDS.128/j), 4 independent accumulators.
// Bounds/grid/constants folded in via warp-level shfl reductions:
//   minx/maxx = min/max over BOTH coords of history POINT 0 (all batches)
//   miny/maxy = min/max over BOTH coords of history POINT 1 (all batches)
// ---------------------------------------------------------------------------
__global__ void k_base(const float* __restrict__ itime,
                       const float* __restrict__ hist,
                       const float* __restrict__ beta_p,
                       const float* __restrict__ logsig_p) {
    __shared__ float4 tab[128];
    __shared__ float xl[NG], yl[NG];
    __shared__ float bounds[4];  // minx, maxx, miny, maxy

    const int b  = blockIdx.y;
    const int js = blockIdx.z;
    const int t  = threadIdx.x;
    const int w  = t >> 5, lane = t & 31;

    // ---- bounds: warp w (w in {0,1}) reduces history point index w ----
    if (w < 2) {
        float a0 = hist[lane * (HH * 2) + 2 * w + 0];
        float a1 = hist[lane * (HH * 2) + 2 * w + 1];
        float b0 = hist[(lane + 32) * (HH * 2) + 2 * w + 0];
        float b1 = hist[(lane + 32) * (HH * 2) + 2 * w + 1];
        float mn = fminf(fminf(a0, a1), fminf(b0, b1));
        float mx = fmaxf(fmaxf(a0, a1), fmaxf(b0, b1));
#pragma unroll
        for (int o = 16; o; o >>= 1) {
            mn = fminf(mn, __shfl_xor_sync(0xffffffffu, mn, o));
            mx = fmaxf(mx, __shfl_xor_sync(0xffffffffu, mx, o));
        }
        if (lane == 0) { bounds[2 * w] = mn; bounds[2 * w + 1] = mx; }
    }

    const float beta = beta_p[0];
    const float sig  = __expf(logsig_p[0]);
    const float c2   = (0.5f / (sig * sig)) * LOG2E_F;

    // ---- packed history tile for this j-chunk ----
    {
        int j = js * 128 + t;
        float hx = hist[b * (HH * 2) + 2 * j];
        float hy = hist[b * (HH * 2) + 2 * j + 1];
        float bt = beta * itime[b * HH + j] * LOG2E_F;
        tab[t] = make_float4(hx, hy, bt, 0.f);
    }
    __syncthreads();

    if (t < NG) {
        float minx = bounds[0], maxx = bounds[1];
        float miny = bounds[2], maxy = bounds[3];
        float fx = (t == NG - 1) ? maxx : minx + (maxx - minx) * ((float)t / (float)(NG - 1));
        float fy = (t == NG - 1) ? maxy : miny + (maxy - miny) * ((float)t / (float)(NG - 1));
        xl[t] = fx; yl[t] = fy;
        if (blockIdx.x == 0 && blockIdx.y == 0 && blockIdx.z == 0) {
            g_xlim[t] = fx; g_ylim[t] = fy;
        }
    }
    if (t == 0 && blockIdx.x == 0 && blockIdx.y == 0 && blockIdx.z == 0) {
        g_c2 = c2; g_beta = beta;
    }
    __syncthreads();

    if (t < 125) {
        int k = blockIdx.x * 125 + t;
        float cx = xl[k % NG];
        float cy = yl[k / NG];
        float a0 = 0.f, a1 = 0.f, a2 = 0.f, a3 = 0.f;
#pragma unroll 4
        for (int j = 0; j < 128; j += 4) {
            float4 v0 = tab[j + 0];
            float4 v1 = tab[j + 1];
            float4 v2 = tab[j + 2];
            float4 v3 = tab[j + 3];
            float dx0 = cx - v0.x, dy0 = cy - v0.y;
            float dx1 = cx - v1.x, dy1 = cy - v1.y;
            float dx2 = cx - v2.x, dy2 = cy - v2.y;
            float dx3 = cx - v3.x, dy3 = cy - v3.y;
            a0 += ex2f(fmaf(-c2, fmaf(dx0, dx0, dy0 * dy0), v0.z));
            a1 += ex2f(fmaf(-c2, fmaf(dx1, dx1, dy1 * dy1), v1.z));
            a2 += ex2f(fmaf(-c2, fmaf(dx2, dx2, dy2 * dy2), v2.z));
            a3 += ex2f(fmaf(-c2, fmaf(dx3, dx3, dy3 * dy3), v3.z));
        }
        g_Spart[js][b * CAND + k] = (a0 + a1) + (a2 + a3);
    }
}

// ---------------------------------------------------------------------------
// Kernel 2: 16-step sequential argmin loop. 128 threads (4 warps) per batch,
// 5 candidates per thread (k = t + 128*r). argmin(ll) == argmin(S);
// first-index tie-break via packed (float_bits(S)<<32 | k) min (S >= 0).
// Sums the 3 j-split partials at load. Initializes out[b] with logp0 +
// constant terms for k_gmm's atomics.
// ---------------------------------------------------------------------------
__global__ void k_iter(const float* __restrict__ curr,
                       const float* __restrict__ hist,
                       const float* __restrict__ logsig_p,
                       float* __restrict__ out) {
    __shared__ unsigned long long wmin[4];
    __shared__ unsigned long long sbest;
    const int b = blockIdx.x;
    const int t = threadIdx.x;  // 128
    const int w = t >> 5, lane = t & 31;
    const float c2 = g_c2, beta = g_beta;

    if (t == 0) {
        float x0 = hist[b * (HH * 2)];
        float y0 = hist[b * (HH * 2) + 1];
        float ls = logsig_p[0];
        float C = 2.f * ls + LOG2PI_F;
        out[b] = -0.5f * (x0 * x0 + y0 * y0) - LOG2PI_F - (float)(LF - 1) * C;
    }

    const int NR = 5;  // ceil(625/128)
    float s[NR], cx[NR], cy[NR];
#pragma unroll
    for (int r = 0; r < NR; r++) {
        int k = t + 128 * r;
        if (k < CAND) {
            cx[r] = g_xlim[k % NG];
            cy[r] = g_ylim[k / NG];
            s[r]  = g_Spart[0][b * CAND + k]
                  + g_Spart[1][b * CAND + k]
                  + g_Spart[2][b * CAND + k];
        } else {
            s[r] = 0.f; cx[r] = 0.f; cy[r] = 0.f;
        }
    }

    for (int i = 0; i < NPLT; i++) {
        unsigned long long best = 0xFFFFFFFFFFFFFFFFULL;
#pragma unroll
        for (int r = 0; r < NR; r++) {
            int k = t + 128 * r;
            if (k < CAND) {
                unsigned long long key =
                    (((unsigned long long)__float_as_uint(s[r])) << 32) | (unsigned)k;
                best = (key < best) ? key : best;
            }
        }
#pragma unroll
        for (int o = 16; o; o >>= 1) {
            unsigned long long other = __shfl_xor_sync(0xffffffffu, best, o);
            best = (other < best) ? other : best;
        }
        if (lane == 0) wmin[w] = best;
        __syncthreads();
        if (t == 0) {
            unsigned long long m = wmin[0];
            m = (wmin[1] < m) ? wmin[1] : m;
            m = (wmin[2] < m) ? wmin[2] : m;
            m = (wmin[3] < m) ? wmin[3] : m;
            sbest = m;
        }
        __syncthreads();

        unsigned idx = (unsigned)(sbest & 0xffffffffu);
        float px = g_xlim[idx % NG];
        float py = g_ylim[idx / NG];

        if (t == 0) {
            out[BB + (i * BB + b) * 2 + 0] = px;
            out[BB + (i * BB + b) * 2 + 1] = py;
            g_pred[(b * NPLT + i) * 2 + 0] = px;
            g_pred[(b * NPLT + i) * 2 + 1] = py;
        }
        if (i < NPLT - 1) {
            float bt = beta * __ldg(&curr[b * NPLT + i]) * LOG2E_F;
#pragma unroll
            for (int r = 0; r < NR; r++) {
                float dx = cx[r] - px;
                float dy = cy[r] - py;
                float sq = fmaf(dx, dx, dy * dy);
                s[r] += ex2f(fmaf(-c2, sq, bt));
            }
        }
        __syncthreads();  // protect wmin/sbest reuse next iteration
    }
}

// ---------------------------------------------------------------------------
// Kernel 3: final GMM log-likelihood.
//   logp_i = log(sum_{j<i} e_j * g_ij) - log(sum_{j<i} e_j) - C
// with e_j = exp(beta*t_j) precomputed (exp(-beta*t_i) cancels),
// g_ij = exp(-c*sq). Grid (16 chunks, 64 batches), 128 thr, warp-per-row
// round-robin stride 64; one atomicAdd per block into out[b].
// ---------------------------------------------------------------------------
__global__ void k_gmm(const float* __restrict__ itime,
                      const float* __restrict__ hist,
                      const float* __restrict__ curr,
                      float* __restrict__ out) {
    __shared__ float exj[LF], px[LF], py[LF];
    __shared__ float wacc[4];
    const int b = blockIdx.y;
    const int c = blockIdx.x;   // 16 chunks
    const int t = threadIdx.x;  // 128
    const float beta = g_beta, c2 = g_c2;

    for (int j = t; j < HH; j += 128) {
        px[j]  = hist[b * (HH * 2) + 2 * j];
        py[j]  = hist[b * (HH * 2) + 2 * j + 1];
        exj[j] = ex2f(beta * itime[b * HH + j] * LOG2E_F);
    }
    if (t < NPLT) {
        px[HH + t]  = g_pred[(b * NPLT + t) * 2 + 0];
        py[HH + t]  = g_pred[(b * NPLT + t) * 2 + 1];
        exj[HH + t] = ex2f(beta * curr[b * NPLT + t] * LOG2E_F);
    }
    __syncthreads();

    const int w = t >> 5, lane = t & 31;
    float acc = 0.f;

    for (int i = 1 + c * 4 + w; i < LF; i += 64) {
        float xi = px[i], yi = py[i];
        float s1 = 0.f, s2 = 0.f;
        for (int j = lane; j < i; j += 32) {
            float e = exj[j];
            float dx = xi - px[j];
            float dy = yi - py[j];
            float sq = fmaf(dx, dx, dy * dy);
            s1 += e;
            s2 = fmaf(e, ex2f(-c2 * sq), s2);
        }
#pragma unroll
        for (int o = 16; o; o >>= 1) {
            s1 += __shfl_down_sync(0xffffffffu, s1, o);
            s2 += __shfl_down_sync(0xffffffffu, s2, o);
        }
        if (lane == 0) acc += __logf(s2) - __logf(s1);
    }
    if (lane == 0) wacc[w] = acc;
    __syncthreads();
    if (t == 0) {
        float tot = (wacc[0] + wacc[1]) + (wacc[2] + wacc[3]);
        atomicAdd(&out[b], tot);
    }
}

// ---------------------------------------------------------------------------
extern "C" void kernel_launch(void* const* d_in, const int* in_sizes, int n_in,
                              void* d_out, int out_size) {
    const float* curr   = (const float*)d_in[0];  // (64,16)
    const float* itime  = (const float*)d_in[1];  // (64,384)
    const float* hist   = (const float*)d_in[2];  // (64,384,2)
    // d_in[3..5] (expected_data, aux_*) are dead inputs
    const float* beta   = (const float*)d_in[6];
    const float* logsig = (const float*)d_in[7];
    float* out = (float*)d_out;  // [64 loglik][16*64*2 predicted]

    k_base<<<dim3(5, BB, JS), 128>>>(itime, hist, beta, logsig);
    k_iter<<<BB, 128>>>(curr, hist, logsig, out);
    k_gmm<<<dim3(16, BB), 128>>>(itime, hist, curr, out);
}